// round 3
// baseline (speedup 1.0000x reference)
#include <cuda_runtime.h>

#define IMG_H 256
#define IMG_W 256
#define NFILT 64
#define NBATCH 32

// Each block: batch b, 4 consecutive rows, all 256 cols, all 64 filters.
// Each thread: one float4 (4 consecutive x) for all 64 filters.
__global__ __launch_bounds__(256, 4) void spiking_conv_kernel(
    const float* __restrict__ tj,     // (32,1,256,256)
    const float* __restrict__ kern,   // (64,1,3,3)
    const float* __restrict__ Bv,     // (64,1)
    const float* __restrict__ D_i,    // (9,64), only row 0 used
    float* __restrict__ out)          // (32,64,256,256)
{
    __shared__ float ws[NFILT * 9];
    __shared__ float sbias[NFILT];

    const int tid = threadIdx.x;
    for (int i = tid; i < NFILT * 9; i += 256) ws[i] = kern[i];
    if (tid < NFILT) {
        // threshold = 1 - D_i[0,f]; ti = conv + threshold - B[f]; clamp at 1
        sbias[tid] = 1.0f - D_i[tid] - Bv[tid];
    }
    __syncthreads();

    const int b  = blockIdx.x >> 6;        // blockIdx / 64
    const int rg = blockIdx.x & 63;        // row-group
    const int y  = rg * 4 + (tid >> 6);    // output row
    const int x0 = (tid & 63) << 2;        // first of 4 output cols

    const float* img = tj + (size_t)b * IMG_H * IMG_W;

    // 3x6 input patch (zero pad == t_min pad since t_min = 0)
    float in[3][6];
#pragma unroll
    for (int r = 0; r < 3; r++) {
        const int yy = y - 1 + r;
        if (yy >= 0 && yy < IMG_H) {
            const float* row = img + yy * IMG_W;
            in[r][0] = (x0 > 0) ? __ldg(row + x0 - 1) : 0.0f;
            float4 m = *reinterpret_cast<const float4*>(row + x0);
            in[r][1] = m.x; in[r][2] = m.y; in[r][3] = m.z; in[r][4] = m.w;
            in[r][5] = (x0 + 4 < IMG_W) ? __ldg(row + x0 + 4) : 0.0f;
        } else {
#pragma unroll
            for (int c = 0; c < 6; c++) in[r][c] = 0.0f;
        }
    }

    float* po = out + (size_t)b * NFILT * IMG_H * IMG_W
                    + (size_t)y * IMG_W + x0;

#pragma unroll 4
    for (int f = 0; f < NFILT; f++) {
        const float* w = &ws[f * 9];
        const float bc = sbias[f];
        float a0 = bc, a1 = bc, a2 = bc, a3 = bc;
#pragma unroll
        for (int r = 0; r < 3; r++) {
#pragma unroll
            for (int c = 0; c < 3; c++) {
                const float wv = w[r * 3 + c];
                a0 = fmaf(wv, in[r][c + 0], a0);
                a1 = fmaf(wv, in[r][c + 1], a1);
                a2 = fmaf(wv, in[r][c + 2], a2);
                a3 = fmaf(wv, in[r][c + 3], a3);
            }
        }
        float4 acc;
        acc.x = fminf(a0, 1.0f);
        acc.y = fminf(a1, 1.0f);
        acc.z = fminf(a2, 1.0f);
        acc.w = fminf(a3, 1.0f);
        *reinterpret_cast<float4*>(po + (size_t)f * IMG_H * IMG_W) = acc;
    }
}

extern "C" void kernel_launch(void* const* d_in, const int* in_sizes, int n_in,
                              void* d_out, int out_size) {
    const float* tj   = (const float*)d_in[0];  // 32*1*256*256
    const float* kern = (const float*)d_in[1];  // 64*1*3*3
    const float* Bv   = (const float*)d_in[2];  // 64*1
    const float* D_i  = (const float*)d_in[3];  // 9*64
    float* out = (float*)d_out;                 // 32*64*256*256

    spiking_conv_kernel<<<NBATCH * 64, 256>>>(tj, kern, Bv, D_i, out);
}